// round 2
// baseline (speedup 1.0000x reference)
#include <cuda_runtime.h>

#define S_ 8
#define U_ 32
#define V_ 32
#define C_ 32
#define SU 256   // S_*U_
#define SV 256   // S_*V_
#define CHUNK 8
#define TROWS 128

// Each thread owns (s, v-pair). Packed f32x2 FMA: acc = {out[v0], out[v1]}.
// W pair {W[u,v0],W[u,v1]} contiguous in global -> 32 packed regs per thread,
// premultiplied by coefficients[s]. x staged in SMEM duplicated {x,x} so the
// compute loop is pure LDS.128 + FFMA2 (no packing ALU work).
__global__ __launch_bounds__(256, 2)
void idxlin_kernel(const float* __restrict__ W,     // (C, S*U*V)
                   const float* __restrict__ X,     // (Z, S*U)
                   const int*   __restrict__ counts,
                   const float* __restrict__ coef,
                   float* __restrict__ out,         // (Z, S*V)
                   int Z)
{
    __shared__ float2 x_sh[CHUNK * SU];   // duplicated x, 16 KB
    __shared__ int segStart[C_ + 1];

    const int tid = threadIdx.x;
    if (tid == 0) {
        int acc = 0;
        segStart[0] = 0;
        #pragma unroll
        for (int c = 0; c < C_; ++c) { acc += counts[c]; segStart[c + 1] = acc; }
    }
    __syncthreads();

    const int lane = tid & 31;
    const int ric_stage = tid >> 5;        // staging row-in-chunk 0..7
    const int vp = tid & 15;               // v-pair index
    const int s  = (tid >> 4) & 7;
    const int rg = tid >> 7;               // row-group half 0/1

    const int blockStart = blockIdx.x * TROWS;
    const int blockEnd   = min(blockStart + TROWS, Z);

    unsigned long long w2[U_];             // packed {W[u,v0]*c, W[u,v1]*c}

    int cur = blockStart;
    int seg = 0;
    while (seg < C_ - 1 && segStart[seg + 1] <= cur) seg++;

    while (cur < blockEnd) {
        const int segTop = (seg < C_ - 1) ? segStart[seg + 1] : Z;
        const int segEnd = min(segTop, blockEnd);

        if (segEnd > cur) {
            // Load + premultiply weights for this segment.
            const float c0 = coef[s];
            const float2* wp = reinterpret_cast<const float2*>(
                W + (size_t)seg * (S_ * U_ * V_) + s * (U_ * V_) + vp * 2);
            #pragma unroll
            for (int u = 0; u < U_; ++u) {
                float2 w = wp[u * (V_ / 2)];
                w.x *= c0; w.y *= c0;
                w2[u] = *reinterpret_cast<unsigned long long*>(&w);
            }

            for (int r0 = cur; r0 < segEnd; r0 += CHUNK) {
                const int nr = min(CHUNK, segEnd - r0);
                __syncthreads();
                // Stage nr rows, duplicated. Consecutive lanes -> consecutive u:
                // STS.64 banks = 2*lane mod 32, conflict-free per half-warp.
                if (ric_stage < nr) {
                    const float* xr = X + (size_t)(r0 + ric_stage) * SU;
                    #pragma unroll
                    for (int k = 0; k < SU / 32; ++k) {
                        float v = xr[lane + 32 * k];
                        x_sh[ric_stage * SU + lane + 32 * k] = make_float2(v, v);
                    }
                }
                __syncthreads();

                const int rbeg = rg * (CHUNK / 2);
                #pragma unroll
                for (int rr = 0; rr < CHUNK / 2; ++rr) {
                    const int ric = rbeg + rr;
                    if (ric >= nr) break;
                    const float4* xs = reinterpret_cast<const float4*>(
                        &x_sh[ric * SU + s * U_]);
                    unsigned long long acc0 = 0ULL, acc1 = 0ULL; // {0.f,0.f}
                    #pragma unroll
                    for (int i = 0; i < U_ / 2; ++i) {
                        float4 q = xs[i];  // {x[2i],x[2i], x[2i+1],x[2i+1]}
                        unsigned long long xa = *reinterpret_cast<unsigned long long*>(&q.x);
                        unsigned long long xb = *reinterpret_cast<unsigned long long*>(&q.z);
                        asm("fma.rn.f32x2 %0, %1, %2, %0;"
                            : "+l"(acc0) : "l"(xa), "l"(w2[2 * i]));
                        asm("fma.rn.f32x2 %0, %1, %2, %0;"
                            : "+l"(acc1) : "l"(xb), "l"(w2[2 * i + 1]));
                    }
                    unsigned long long accr;
                    asm("add.rn.f32x2 %0, %1, %2;"
                        : "=l"(accr) : "l"(acc0), "l"(acc1));
                    float2 res = *reinterpret_cast<float2*>(&accr);
                    *reinterpret_cast<float2*>(
                        out + (size_t)(r0 + ric) * SV + s * V_ + vp * 2) = res;
                }
            }
        }
        cur = segEnd > cur ? segEnd : cur;
        if (cur < blockEnd) {
            seg++;
            if (seg >= C_) break;  // safety (counts undersum)
        }
    }
}

extern "C" void kernel_launch(void* const* d_in, const int* in_sizes, int n_in,
                              void* d_out, int out_size) {
    const float* W      = (const float*)d_in[0];   // input1 (C, S*U*V)
    const float* X      = (const float*)d_in[1];   // input2 (Z, S*U)
    const int*   counts = (const int*)d_in[2];
    const float* coef   = (const float*)d_in[3];
    float* out = (float*)d_out;

    int Z = in_sizes[1] / SU;
    int grid = (Z + TROWS - 1) / TROWS;
    idxlin_kernel<<<grid, 256>>>(W, X, counts, coef, out, Z);
}